// round 14
// baseline (speedup 1.0000x reference)
#include <cuda_runtime.h>
#include <cuda_fp16.h>
#include <cstdint>
#include <cstddef>

// Problem shape (fixed): B=8, L=4096, D=1024, DK=1024
#define BATCH 8
#define SEQ   4096
#define DIM   1024
#define NCOLS 2048
#define NROWS (BATCH * SEQ)               // 32768
#define K2DIM (DIM / 2)                   // 512 half2 per A row
#define NK2   (DIM / 2)                   // 512 k2 rows in W

// GEMM: block 128x128, 8 warps (4Mx2N), BK=16 (one k16 mma step/stage), 4-stage cp.async
// Stage layout (bytes): AH[128 rows x 48B] | AL | BH[8 rows x 544B] | BL
#define AROW_B   48                       // A smem row stride bytes (32B data + 16 pad)
#define BROW_B   544                      // B smem row stride bytes (512B data + 32 pad)
#define OFF_AL_B 6144
#define OFF_BH_B 12288
#define OFF_BL_B 16640
#define STAGE_B  20992
#define STAGE_U  (STAGE_B / 4)            // 5248 uint32
#define SMEM_BYTES (4 * STAGE_B)          // 83968

// ---------------------------------------------------------------------------
// Scratch (no cudaMalloc allowed)
// ---------------------------------------------------------------------------
__device__ float    g_qk[(size_t)NROWS * NCOLS];     // 256 MiB
__device__ uint32_t g_Ah[(size_t)NROWS * K2DIM];     // 64 MiB  [m][k2] half2
__device__ uint32_t g_Al[(size_t)NROWS * K2DIM];     // 64 MiB
__device__ uint32_t g_Wh[(size_t)NK2 * NCOLS];       // 4 MiB   [k2][n] half2
__device__ uint32_t g_Wl[(size_t)NK2 * NCOLS];       // 4 MiB
__device__ float    g_probs[NROWS];
__device__ int      g_bpos[NROWS];
__device__ int      g_nc[BATCH];
__device__ float    g_aux[BATCH];

// ---------------------------------------------------------------------------
// Helpers
// ---------------------------------------------------------------------------
__device__ __forceinline__ uint32_t f2h2(float lo, float hi) {
    half2 h = __floats2half2_rn(lo, hi);
    return *reinterpret_cast<uint32_t*>(&h);
}
__device__ __forceinline__ float h1f(float a) {
    return __half2float(__float2half_rn(a));
}
__device__ __forceinline__ void cp16(uint32_t dst, const void* src) {
    asm volatile("cp.async.cg.shared.global [%0], [%1], 16;"
                 :: "r"(dst), "l"(src));
}
__device__ __forceinline__ void ldsm4(uint32_t* r, uint32_t addr) {
    asm volatile("ldmatrix.sync.aligned.m8n8.x4.shared.b16 {%0,%1,%2,%3}, [%4];"
                 : "=r"(r[0]), "=r"(r[1]), "=r"(r[2]), "=r"(r[3]) : "r"(addr));
}
// d += a(16x16 f16) * b(16x8 f16), fp32 accumulate
__device__ __forceinline__ void mma16(float* d, const uint32_t* a, const uint32_t* b) {
    asm volatile(
        "mma.sync.aligned.m16n8k16.row.col.f32.f16.f16.f32 "
        "{%0,%1,%2,%3}, {%4,%5,%6,%7}, {%8,%9}, {%0,%1,%2,%3};"
        : "+f"(d[0]), "+f"(d[1]), "+f"(d[2]), "+f"(d[3])
        : "r"(a[0]), "r"(a[1]), "r"(a[2]), "r"(a[3]), "r"(b[0]), "r"(b[1]));
}

// ---------------------------------------------------------------------------
// Prepass 1: split W -> Wh/Wl packed [k2][n] half2 (low half = even k)
// ---------------------------------------------------------------------------
__global__ void split_w(const float* __restrict__ W)
{
    const int idx = blockIdx.x * blockDim.x + threadIdx.x;   // 0 .. 512*1024-1
    const int k2 = idx >> 9;
    const int n4 = (idx & 511) * 4;
    float4 r0 = *reinterpret_cast<const float4*>(W + (size_t)(2 * k2) * NCOLS + n4);
    float4 r1 = *reinterpret_cast<const float4*>(W + (size_t)(2 * k2 + 1) * NCOLS + n4);
    float e0[4] = {r0.x, r0.y, r0.z, r0.w};
    float e1[4] = {r1.x, r1.y, r1.z, r1.w};
    uint32_t hh[4], ll[4];
#pragma unroll
    for (int j = 0; j < 4; j++) {
        float h0 = h1f(e0[j]), h1 = h1f(e1[j]);
        hh[j] = f2h2(h0, h1);
        ll[j] = f2h2(e0[j] - h0, e1[j] - h1);
    }
    *reinterpret_cast<uint4*>(g_Wh + (size_t)k2 * NCOLS + n4) =
        make_uint4(hh[0], hh[1], hh[2], hh[3]);
    *reinterpret_cast<uint4*>(g_Wl + (size_t)k2 * NCOLS + n4) =
        make_uint4(ll[0], ll[1], ll[2], ll[3]);
}

// ---------------------------------------------------------------------------
// Prepass 2: split A -> Ah/Al packed [m][k2] half2 (low half = even k)
// ---------------------------------------------------------------------------
__global__ void split_a(const float* __restrict__ A)
{
    const int idx = blockIdx.x * blockDim.x + threadIdx.x;   // 0 .. NROWS*256-1
    const int m  = idx >> 8;
    const int kq = idx & 255;
    float4 v = *reinterpret_cast<const float4*>(A + (size_t)m * DIM + kq * 4);
    float e[4] = {v.x, v.y, v.z, v.w};
    float h[4];
#pragma unroll
    for (int j = 0; j < 4; j++) h[j] = h1f(e[j]);
    *reinterpret_cast<uint2*>(g_Ah + (size_t)m * K2DIM + kq * 2) =
        make_uint2(f2h2(h[0], h[1]), f2h2(h[2], h[3]));
    *reinterpret_cast<uint2*>(g_Al + (size_t)m * K2DIM + kq * 2) =
        make_uint2(f2h2(e[0] - h[0], e[1] - h[1]), f2h2(e[2] - h[2], e[3] - h[3]));
}

// ---------------------------------------------------------------------------
// Kernel: 3-pass fp16-split GEMM, cp.async 4-stage, ldmatrix A frags
// grid (NCOLS/128=16, NROWS/128=256), 256 threads
// ---------------------------------------------------------------------------
__global__ void __launch_bounds__(256, 1)
gemm_mma()
{
    extern __shared__ uint32_t sm[];
    const uint32_t smem_base = (uint32_t)__cvta_generic_to_shared(sm);

    const int tid  = threadIdx.x;
    const int lane = tid & 31;
    const int wid  = tid >> 5;
    const int wm   = wid & 3;
    const int wn   = wid >> 2;
    const int bm   = blockIdx.y * 128;
    const int bn   = blockIdx.x * 128;

    const int g  = lane >> 2;
    const int tg = lane & 3;

    float acc[2][8][4];
#pragma unroll
    for (int mt = 0; mt < 2; mt++)
#pragma unroll
        for (int nt = 0; nt < 8; nt++)
#pragma unroll
            for (int j = 0; j < 4; j++) acc[mt][nt][j] = 0.f;

    // cp.async decomposition (4 chunks/thread)
    const int a_row  = tid >> 1;          // 0..127
    const int a_part = tid & 1;           // 16B chunk within 32B row
    const int b_row  = tid >> 5;          // 0..7
    const int b_cc   = tid & 31;          // 16B chunk within 512B row

    auto issue = [&](int s) {
        const uint32_t st = smem_base + (uint32_t)((s & 3) * STAGE_B);
        const int k2_0 = s * 8;
        cp16(st + a_row * AROW_B + a_part * 16,
             g_Ah + (size_t)(bm + a_row) * K2DIM + k2_0 + a_part * 4);
        cp16(st + OFF_AL_B + a_row * AROW_B + a_part * 16,
             g_Al + (size_t)(bm + a_row) * K2DIM + k2_0 + a_part * 4);
        cp16(st + OFF_BH_B + b_row * BROW_B + b_cc * 16,
             g_Wh + (size_t)(k2_0 + b_row) * NCOLS + bn + b_cc * 4);
        cp16(st + OFF_BL_B + b_row * BROW_B + b_cc * 16,
             g_Wl + (size_t)(k2_0 + b_row) * NCOLS + bn + b_cc * 4);
    };

    // ldmatrix lane address components
    const int lrow = lane & 15;
    const int lcol = (lane >> 4) * 16;    // 0 or 16 bytes (k2 0-3 vs 4-7)

    // Prologue: fill 3 stages
#pragma unroll
    for (int s = 0; s < 3; s++) {
        issue(s);
        asm volatile("cp.async.commit_group;" ::: "memory");
    }

    const int NST = DIM / 16;   // 64
    for (int s = 0; s < NST; s++) {
        asm volatile("cp.async.wait_group %0;" :: "n"(2) : "memory");
        __syncthreads();
        if (s + 3 < NST) issue(s + 3);
        asm volatile("cp.async.commit_group;" ::: "memory");

        const uint32_t* base = sm + (s & 3) * STAGE_U;
        const uint32_t abase = smem_base + (uint32_t)((s & 3) * STAGE_B);

        uint32_t ah[2][4], al[2][4], bh[8][2], bl[8][2];
#pragma unroll
        for (int mt = 0; mt < 2; mt++) {
            const uint32_t ad = abase + (wm * 32 + mt * 16 + lrow) * AROW_B + lcol;
            ldsm4(ah[mt], ad);
            ldsm4(al[mt], ad + OFF_AL_B);
        }
#pragma unroll
        for (int nt = 0; nt < 8; nt++) {
            const int n = wn * 64 + nt * 8 + g;
            bh[nt][0] = base[OFF_BH_B / 4 + tg * (BROW_B / 4) + n];
            bh[nt][1] = base[OFF_BH_B / 4 + (tg + 4) * (BROW_B / 4) + n];
            bl[nt][0] = base[OFF_BL_B / 4 + tg * (BROW_B / 4) + n];
            bl[nt][1] = base[OFF_BL_B / 4 + (tg + 4) * (BROW_B / 4) + n];
        }

        // pass 1: hi*hi
#pragma unroll
        for (int nt = 0; nt < 8; nt++)
#pragma unroll
            for (int mt = 0; mt < 2; mt++) mma16(acc[mt][nt], ah[mt], bh[nt]);
        // pass 2: hi*lo
#pragma unroll
        for (int nt = 0; nt < 8; nt++)
#pragma unroll
            for (int mt = 0; mt < 2; mt++) mma16(acc[mt][nt], ah[mt], bl[nt]);
        // pass 3: lo*hi
#pragma unroll
        for (int nt = 0; nt < 8; nt++)
#pragma unroll
            for (int mt = 0; mt < 2; mt++) mma16(acc[mt][nt], al[mt], bh[nt]);
    }

    // Epilogue: C fragment -> g_qk
#pragma unroll
    for (int mt = 0; mt < 2; mt++) {
        const int r0 = bm + wm * 32 + mt * 16 + g;
#pragma unroll
        for (int nt = 0; nt < 8; nt++) {
            const int c = bn + wn * 64 + nt * 8 + tg * 2;
            *reinterpret_cast<float2*>(g_qk + (size_t)r0 * NCOLS + c) =
                make_float2(acc[mt][nt][0], acc[mt][nt][1]);
            *reinterpret_cast<float2*>(g_qk + (size_t)(r0 + 8) * NCOLS + c) =
                make_float2(acc[mt][nt][2], acc[mt][nt][3]);
        }
    }
}

// ---------------------------------------------------------------------------
// Kernel: one warp per token — cosine(q_l, k_{l-1}) -> probs
// ---------------------------------------------------------------------------
__global__ void cos_kernel(const float* __restrict__ start_key)
{
    const int gw   = (blockIdx.x * blockDim.x + threadIdx.x) >> 5;
    const int lane = threadIdx.x & 31;
    if (gw >= NROWS) return;
    const int l = gw & (SEQ - 1);

    const float4* q = reinterpret_cast<const float4*>(g_qk + (size_t)gw * NCOLS);
    const float4* kp = (l == 0)
        ? reinterpret_cast<const float4*>(start_key)
        : reinterpret_cast<const float4*>(g_qk + (size_t)(gw - 1) * NCOLS + DIM);

    float dot = 0.f, qq = 0.f, kk = 0.f;
#pragma unroll
    for (int i = 0; i < 8; i++) {
        float4 qv = q[lane + i * 32];
        float4 kv = kp[lane + i * 32];
        dot += qv.x * kv.x + qv.y * kv.y + qv.z * kv.z + qv.w * kv.w;
        qq  += qv.x * qv.x + qv.y * qv.y + qv.z * qv.z + qv.w * qv.w;
        kk  += kv.x * kv.x + kv.y * kv.y + kv.z * kv.z + kv.w * kv.w;
    }
#pragma unroll
    for (int o = 16; o; o >>= 1) {
        dot += __shfl_xor_sync(0xffffffffu, dot, o);
        qq  += __shfl_xor_sync(0xffffffffu, qq,  o);
        kk  += __shfl_xor_sync(0xffffffffu, kk,  o);
    }
    if (lane == 0) {
        float qn = fmaxf(sqrtf(qq), 1e-8f);
        float kn = fmaxf(sqrtf(kk), 1e-8f);
        float cs = dot / (qn * kn);
        g_probs[gw] = (1.0f - cs) * 0.5f;
    }
}

// ---------------------------------------------------------------------------
// Kernel: per-batch boundary scan/compaction, chunk_lens, aux partials
// ---------------------------------------------------------------------------
__global__ void __launch_bounds__(1024, 1)
scan_kernel(float* __restrict__ out_cl)
{
    const int b = blockIdx.x;
    const int tid = threadIdx.x;
    const int lane = tid & 31, wid = tid >> 5;

    __shared__ int   warp_c[32];
    __shared__ float warp_s[32];
    __shared__ int   s_nc;
    __shared__ float s_G;

    const float* pr = g_probs + b * SEQ;
    float4 p4 = reinterpret_cast<const float4*>(pr)[tid];
    float p[4] = {p4.x, p4.y, p4.z, p4.w};

    int m[4]; int cnt = 0; float psum = 0.f;
#pragma unroll
    for (int i = 0; i < 4; i++) {
        int l = tid * 4 + i;
        m[i] = (p[i] > 0.5f) || (l == 0);
        cnt += m[i];
        psum += p[i];
    }

    int inc = cnt;
#pragma unroll
    for (int o = 1; o < 32; o <<= 1) {
        int v = __shfl_up_sync(0xffffffffu, inc, o);
        if (lane >= o) inc += v;
    }
    float ws = psum;
#pragma unroll
    for (int o = 16; o; o >>= 1) ws += __shfl_xor_sync(0xffffffffu, ws, o);

    if (lane == 31) warp_c[wid] = inc;
    if (lane == 0)  warp_s[wid] = ws;
    __syncthreads();

    if (wid == 0) {
        int v = warp_c[lane];
        int iv = v;
#pragma unroll
        for (int o = 1; o < 32; o <<= 1) {
            int t = __shfl_up_sync(0xffffffffu, iv, o);
            if (lane >= o) iv += t;
        }
        float s = warp_s[lane];
#pragma unroll
        for (int o = 16; o; o >>= 1) s += __shfl_xor_sync(0xffffffffu, s, o);
        warp_c[lane] = iv - v;
        if (lane == 31) s_nc = iv;
        if (lane == 0)  s_G  = s;
    }
    __syncthreads();

    int r = warp_c[wid] + (inc - cnt);
#pragma unroll
    for (int i = 0; i < 4; i++) {
        if (m[i]) { g_bpos[b * SEQ + r] = tid * 4 + i; r++; }
    }
    const int nc = s_nc;
    if (tid == 0) {
        g_nc[b] = nc;
        float G  = s_G / (float)SEQ;
        float Fm = (float)nc / (float)SEQ;
        g_aux[b] = 1.2f * (5.0f * Fm * G + (1.0f - Fm) * (1.0f - G));
    }
    __syncthreads();

#pragma unroll
    for (int i = 0; i < 4; i++) {
        int j = tid * 4 + i;
        float v = 0.f;
        if (j < nc) {
            int pj = g_bpos[b * SEQ + j];
            int pn = (j + 1 < nc) ? g_bpos[b * SEQ + j + 1] : SEQ;
            v = (float)(pn - pj);
        }
        out_cl[b * SEQ + j] = v;
    }
}

// ---------------------------------------------------------------------------
// Kernel: downsampled gather + scalar loss
// ---------------------------------------------------------------------------
__global__ void gather_kernel(const float* __restrict__ tokens,
                              float* __restrict__ out_ds,
                              float* __restrict__ out_loss)
{
    const int row = blockIdx.x;
    const int b = row >> 12;
    const int j = row & (SEQ - 1);
    const int tid = threadIdx.x;

    float4* dst = reinterpret_cast<float4*>(out_ds + (size_t)row * DIM);
    if (j < g_nc[b]) {
        int   p = g_bpos[b * SEQ + j];
        float s = g_probs[b * SEQ + p];
        const float4* src = reinterpret_cast<const float4*>(
            tokens + (size_t)(b * SEQ + p) * DIM);
        float4 v0 = src[tid], v1 = src[tid + 128];
        dst[tid]       = make_float4(v0.x * s, v0.y * s, v0.z * s, v0.w * s);
        dst[tid + 128] = make_float4(v1.x * s, v1.y * s, v1.z * s, v1.w * s);
    } else {
        float4 z = make_float4(0.f, 0.f, 0.f, 0.f);
        dst[tid] = z; dst[tid + 128] = z;
    }

    if (row == 0 && tid == 0) {
        float s = 0.f;
#pragma unroll
        for (int i = 0; i < BATCH; i++) s += g_aux[i];
        *out_loss = s * (0.03f / (float)BATCH);
    }
}

// ---------------------------------------------------------------------------
// Launch
// ---------------------------------------------------------------------------
extern "C" void kernel_launch(void* const* d_in, const int* in_sizes, int n_in,
                              void* d_out, int out_size)
{
    const float* tokens    = (const float*)d_in[0];
    const float* W_qk      = (const float*)d_in[1];
    const float* start_key = (const float*)d_in[2];

    float* out      = (float*)d_out;
    float* out_ds   = out;
    float* out_cl   = out + (size_t)NROWS * DIM;
    float* out_loss = out_cl + NROWS;

    cudaFuncSetAttribute(gemm_mma, cudaFuncAttributeMaxDynamicSharedMemorySize,
                         SMEM_BYTES);

    split_w<<<(NK2 * 512) / 256, 256>>>(W_qk);          // 2048 blocks
    split_a<<<(NROWS * 256) / 256, 256>>>(tokens);      // 32768 blocks

    dim3 grid(NCOLS / 128, NROWS / 128);   // (16, 256)
    gemm_mma<<<grid, 256, SMEM_BYTES>>>();
    cos_kernel<<<NROWS / 8, 256>>>(start_key);
    scan_kernel<<<BATCH, 1024>>>(out_cl);
    gather_kernel<<<NROWS, 128>>>(tokens, out_ds, out_loss);

    (void)in_sizes; (void)n_in; (void)out_size;
}

// round 15
// speedup vs baseline: 1.8880x; 1.8880x over previous
#include <cuda_runtime.h>
#include <cuda_fp16.h>
#include <cstdint>
#include <cstddef>

// Problem shape (fixed): B=8, L=4096, D=1024, DK=1024
#define BATCH 8
#define SEQ   4096
#define DIM   1024
#define NCOLS 2048
#define NROWS (BATCH * SEQ)               // 32768

// GEMM tiling: block 128x128, BK=16, 8 warps (4Mx2N), 1-pass fp16 (hi only)
#define KROW   136                        // half2 units per k2-row (128 + 8 pad)
#define OFF_BH (8 * KROW)                 // 1088
#define STG    (16 * KROW)                // 2176 u32 per stage
// static smem: 2 stages = 17408 B

#define REPCAP 1024
#define WINDOW 2.5e-4f

// ---------------------------------------------------------------------------
// Scratch (no cudaMalloc allowed)
// ---------------------------------------------------------------------------
__device__ float    g_qk[(size_t)NROWS * NCOLS];   // 256 MiB
__device__ float    g_probs[NROWS];
__device__ int      g_bpos[NROWS];
__device__ int      g_nc[BATCH];
__device__ float    g_aux[BATCH];
__device__ int      g_rep_cnt;
__device__ int      g_rep_rows[REPCAP];
__device__ float    g_rqk[(size_t)REPCAP * 2048];  // 8 MiB exact q|k per repair row

// ---------------------------------------------------------------------------
// Helpers
// ---------------------------------------------------------------------------
__device__ __forceinline__ uint32_t f2h2(float lo, float hi) {
    half2 h = __floats2half2_rn(lo, hi);
    return *reinterpret_cast<uint32_t*>(&h);
}
__device__ __forceinline__ float h1f(float a) {
    return __half2float(__float2half_rn(a));
}
// d += a(16x16 f16) * b(16x8 f16), fp32 accumulate
__device__ __forceinline__ void mma16(float* d, const uint32_t* a, const uint32_t* b) {
    asm volatile(
        "mma.sync.aligned.m16n8k16.row.col.f32.f16.f16.f32 "
        "{%0,%1,%2,%3}, {%4,%5,%6,%7}, {%8,%9}, {%0,%1,%2,%3};"
        : "+f"(d[0]), "+f"(d[1]), "+f"(d[2]), "+f"(d[3])
        : "r"(a[0]), "r"(a[1]), "r"(a[2]), "r"(a[3]), "r"(b[0]), "r"(b[1]));
}

// ---------------------------------------------------------------------------
// Kernel 1: 1-pass fp16 GEMM (hi parts only)  g_qk = tokens @ W  (fp32 acc)
// grid (16, 256), 256 threads, 2 CTAs/SM
// ---------------------------------------------------------------------------
__global__ void __launch_bounds__(256, 2)
gemm_mma(const float* __restrict__ A, const float* __restrict__ W)
{
    __shared__ uint32_t sm[2 * STG];

    const int tid  = threadIdx.x;
    const int lane = tid & 31;
    const int wid  = tid >> 5;
    const int wm   = wid & 3;
    const int wn   = wid >> 2;
    const int bm   = blockIdx.y * 128;
    const int bn   = blockIdx.x * 128;

    if (blockIdx.x == 0 && blockIdx.y == 0 && tid == 0) g_rep_cnt = 0;

    const int g  = lane >> 2;
    const int tg = lane & 3;

    float acc[2][8][4];
#pragma unroll
    for (int mt = 0; mt < 2; mt++)
#pragma unroll
        for (int nt = 0; nt < 8; nt++)
#pragma unroll
            for (int j = 0; j < 4; j++) acc[mt][nt][j] = 0.f;

    float4 va[2], vb0, vb1;
    const int bj  = tid >> 5;
    const int bn4 = (tid & 31) * 4;

    auto load_regs = [&](int k0) {
#pragma unroll
        for (int i = 0; i < 2; i++) {
            const int c = tid + i * 256;
            va[i] = *reinterpret_cast<const float4*>(
                A + (size_t)(bm + (c >> 2)) * DIM + k0 + (c & 3) * 4);
        }
        vb0 = *reinterpret_cast<const float4*>(
            W + (size_t)(k0 + 2 * bj) * NCOLS + bn + bn4);
        vb1 = *reinterpret_cast<const float4*>(
            W + (size_t)(k0 + 2 * bj + 1) * NCOLS + bn + bn4);
    };

    auto store_smem = [&](int buf) {
        uint32_t* base = sm + buf * STG;
#pragma unroll
        for (int i = 0; i < 2; i++) {
            const int c = tid + i * 256;
            const int row = c >> 2, kq = c & 3;
            float e[4] = {va[i].x, va[i].y, va[i].z, va[i].w};
            base[(2 * kq + 0) * KROW + row] = f2h2(h1f(e[0]), h1f(e[1]));
            base[(2 * kq + 1) * KROW + row] = f2h2(h1f(e[2]), h1f(e[3]));
        }
        {
            float r0[4] = {vb0.x, vb0.y, vb0.z, vb0.w};
            float r1[4] = {vb1.x, vb1.y, vb1.z, vb1.w};
            uint32_t hh[4];
#pragma unroll
            for (int j = 0; j < 4; j++) hh[j] = f2h2(h1f(r0[j]), h1f(r1[j]));
            *reinterpret_cast<uint4*>(base + OFF_BH + bj * KROW + bn4) =
                make_uint4(hh[0], hh[1], hh[2], hh[3]);
        }
    };

    load_regs(0);
    store_smem(0);
    __syncthreads();

    const int NST = DIM / 16;   // 64
    for (int s = 0; s < NST; s++) {
        const int buf = s & 1;
        const uint32_t* base = sm + buf * STG;

        if (s + 1 < NST) load_regs((s + 1) * 16);

        uint32_t ah[2][4], bh[8][2];
#pragma unroll
        for (int mt = 0; mt < 2; mt++) {
            const int m = wm * 32 + mt * 16 + g;
            ah[mt][0] = base[tg * KROW + m];
            ah[mt][1] = base[tg * KROW + m + 8];
            ah[mt][2] = base[(tg + 4) * KROW + m];
            ah[mt][3] = base[(tg + 4) * KROW + m + 8];
        }
#pragma unroll
        for (int nt = 0; nt < 8; nt++) {
            const int n = wn * 64 + nt * 8 + g;
            bh[nt][0] = base[OFF_BH + tg * KROW + n];
            bh[nt][1] = base[OFF_BH + (tg + 4) * KROW + n];
        }

#pragma unroll
        for (int nt = 0; nt < 8; nt++)
#pragma unroll
            for (int mt = 0; mt < 2; mt++) mma16(acc[mt][nt], ah[mt], bh[nt]);

        if (s + 1 < NST) store_smem(buf ^ 1);   // STS under MMA shadow
        __syncthreads();
    }

    // Epilogue: C fragment -> g_qk
#pragma unroll
    for (int mt = 0; mt < 2; mt++) {
        const int r0 = bm + wm * 32 + mt * 16 + g;
#pragma unroll
        for (int nt = 0; nt < 8; nt++) {
            const int c = bn + wn * 64 + nt * 8 + tg * 2;
            *reinterpret_cast<float2*>(g_qk + (size_t)r0 * NCOLS + c) =
                make_float2(acc[mt][nt][0], acc[mt][nt][1]);
            *reinterpret_cast<float2*>(g_qk + (size_t)(r0 + 8) * NCOLS + c) =
                make_float2(acc[mt][nt][2], acc[mt][nt][3]);
        }
    }
}

// ---------------------------------------------------------------------------
// Kernel 2: cosine -> probs; flags borderline rows for exact repair
// ---------------------------------------------------------------------------
__global__ void cos_kernel(const float* __restrict__ start_key)
{
    const int gw   = (blockIdx.x * blockDim.x + threadIdx.x) >> 5;
    const int lane = threadIdx.x & 31;
    if (gw >= NROWS) return;
    const int l = gw & (SEQ - 1);

    const float4* q = reinterpret_cast<const float4*>(g_qk + (size_t)gw * NCOLS);
    const float4* kp = (l == 0)
        ? reinterpret_cast<const float4*>(start_key)
        : reinterpret_cast<const float4*>(g_qk + (size_t)(gw - 1) * NCOLS + DIM);

    float dot = 0.f, qq = 0.f, kk = 0.f;
#pragma unroll
    for (int i = 0; i < 8; i++) {
        float4 qv = q[lane + i * 32];
        float4 kv = kp[lane + i * 32];
        dot += qv.x * kv.x + qv.y * kv.y + qv.z * kv.z + qv.w * kv.w;
        qq  += qv.x * qv.x + qv.y * qv.y + qv.z * qv.z + qv.w * qv.w;
        kk  += kv.x * kv.x + kv.y * kv.y + kv.z * kv.z + kv.w * kv.w;
    }
#pragma unroll
    for (int o = 16; o; o >>= 1) {
        dot += __shfl_xor_sync(0xffffffffu, dot, o);
        qq  += __shfl_xor_sync(0xffffffffu, qq,  o);
        kk  += __shfl_xor_sync(0xffffffffu, kk,  o);
    }
    if (lane == 0) {
        float qn = fmaxf(sqrtf(qq), 1e-8f);
        float kn = fmaxf(sqrtf(kk), 1e-8f);
        float p  = (1.0f - dot / (qn * kn)) * 0.5f;
        g_probs[gw] = p;
        if (l != 0 && fabsf(p - 0.5f) < WINDOW) {
            int idx = atomicAdd(&g_rep_cnt, 1);
            if (idx < REPCAP) g_rep_rows[idx] = gw;
        }
    }
}

// ---------------------------------------------------------------------------
// Kernel 3: gathered exact fp32 GEMM for repair rows
// grid (32, 16): x = 64-col chunk of 2048, y = 64-row chunk of repair list
// ---------------------------------------------------------------------------
__global__ void __launch_bounds__(256, 2)
repair_gemm(const float* __restrict__ tokens, const float* __restrict__ W)
{
    const int cnt = min(g_rep_cnt, REPCAP);
    const int i0  = blockIdx.y * 64;
    if (i0 >= cnt) return;

    const int cb      = blockIdx.x;
    const int colbase = cb * 64;          // W column base (q: <1024, k: >=1024)
    const bool kside  = cb >= 16;

    __shared__ float As[16][72];
    __shared__ float Bs[16][72];
    __shared__ int   srows[64];

    const int tid = threadIdx.x;
    if (tid < 64) {
        int i = i0 + tid;
        int r = g_rep_rows[(i < cnt) ? i : (cnt - 1)];
        srows[tid] = r - (kside ? 1 : 0);  // l != 0 guaranteed for listed rows
    }
    __syncthreads();

    const int ty = tid >> 4, tx = tid & 15;
    float acc[4][4];
#pragma unroll
    for (int r = 0; r < 4; r++)
#pragma unroll
        for (int c = 0; c < 4; c++) acc[r][c] = 0.f;

    const int arow = tid >> 2, kq = tid & 3;
    const int bk = tid >> 4, bn4 = (tid & 15) * 4;

    for (int k0 = 0; k0 < DIM; k0 += 16) {
        {
            float4 v = *reinterpret_cast<const float4*>(
                tokens + (size_t)srows[arow] * DIM + k0 + kq * 4);
            As[kq * 4 + 0][arow] = v.x;
            As[kq * 4 + 1][arow] = v.y;
            As[kq * 4 + 2][arow] = v.z;
            As[kq * 4 + 3][arow] = v.w;
        }
        {
            *reinterpret_cast<float4*>(&Bs[bk][bn4]) =
                *reinterpret_cast<const float4*>(
                    W + (size_t)(k0 + bk) * NCOLS + colbase + bn4);
        }
        __syncthreads();
#pragma unroll
        for (int k = 0; k < 16; k++) {
            float a[4], b[4];
#pragma unroll
            for (int j = 0; j < 4; j++) { a[j] = As[k][ty * 4 + j]; b[j] = Bs[k][tx * 4 + j]; }
#pragma unroll
            for (int r = 0; r < 4; r++)
#pragma unroll
                for (int c = 0; c < 4; c++) acc[r][c] += a[r] * b[c];
        }
        __syncthreads();
    }

#pragma unroll
    for (int r = 0; r < 4; r++) {
        const int li = i0 + ty * 4 + r;
        if (li < cnt) {
#pragma unroll
            for (int c = 0; c < 4; c++)
                g_rqk[(size_t)li * 2048 + colbase + tx * 4 + c] = acc[r][c];
        }
    }
}

// ---------------------------------------------------------------------------
// Kernel 4: exact cosine for repair rows -> overwrite probs
// ---------------------------------------------------------------------------
__global__ void repair_fin()
{
    const int cnt  = min(g_rep_cnt, REPCAP);
    const int w    = (blockIdx.x * blockDim.x + threadIdx.x) >> 5;
    const int lane = threadIdx.x & 31;
    if (w >= cnt) return;

    const float4* q = reinterpret_cast<const float4*>(g_rqk + (size_t)w * 2048);
    const float4* k = reinterpret_cast<const float4*>(g_rqk + (size_t)w * 2048 + 1024);

    float dot = 0.f, qq = 0.f, kk = 0.f;
#pragma unroll
    for (int i = 0; i < 8; i++) {
        float4 qv = q[lane + i * 32];
        float4 kv = k[lane + i * 32];
        dot += qv.x * kv.x + qv.y * kv.y + qv.z * kv.z + qv.w * kv.w;
        qq  += qv.x * qv.x + qv.y * qv.y + qv.z * qv.z + qv.w * qv.w;
        kk  += kv.x * kv.x + kv.y * kv.y + kv.z * kv.z + kv.w * kv.w;
    }
#pragma unroll
    for (int o = 16; o; o >>= 1) {
        dot += __shfl_xor_sync(0xffffffffu, dot, o);
        qq  += __shfl_xor_sync(0xffffffffu, qq,  o);
        kk  += __shfl_xor_sync(0xffffffffu, kk,  o);
    }
    if (lane == 0) {
        float qn = fmaxf(sqrtf(qq), 1e-8f);
        float kn = fmaxf(sqrtf(kk), 1e-8f);
        g_probs[g_rep_rows[w]] = (1.0f - dot / (qn * kn)) * 0.5f;
    }
}

// ---------------------------------------------------------------------------
// Kernel 5: per-batch boundary scan/compaction, chunk_lens, aux partials
// ---------------------------------------------------------------------------
__global__ void __launch_bounds__(1024, 1)
scan_kernel(float* __restrict__ out_cl)
{
    const int b = blockIdx.x;
    const int tid = threadIdx.x;
    const int lane = tid & 31, wid = tid >> 5;

    __shared__ int   warp_c[32];
    __shared__ float warp_s[32];
    __shared__ int   s_nc;
    __shared__ float s_G;

    const float* pr = g_probs + b * SEQ;
    float4 p4 = reinterpret_cast<const float4*>(pr)[tid];
    float p[4] = {p4.x, p4.y, p4.z, p4.w};

    int m[4]; int cnt = 0; float psum = 0.f;
#pragma unroll
    for (int i = 0; i < 4; i++) {
        int l = tid * 4 + i;
        m[i] = (p[i] > 0.5f) || (l == 0);
        cnt += m[i];
        psum += p[i];
    }

    int inc = cnt;
#pragma unroll
    for (int o = 1; o < 32; o <<= 1) {
        int v = __shfl_up_sync(0xffffffffu, inc, o);
        if (lane >= o) inc += v;
    }
    float ws = psum;
#pragma unroll
    for (int o = 16; o; o >>= 1) ws += __shfl_xor_sync(0xffffffffu, ws, o);

    if (lane == 31) warp_c[wid] = inc;
    if (lane == 0)  warp_s[wid] = ws;
    __syncthreads();

    if (wid == 0) {
        int v = warp_c[lane];
        int iv = v;
#pragma unroll
        for (int o = 1; o < 32; o <<= 1) {
            int t = __shfl_up_sync(0xffffffffu, iv, o);
            if (lane >= o) iv += t;
        }
        float s = warp_s[lane];
#pragma unroll
        for (int o = 16; o; o >>= 1) s += __shfl_xor_sync(0xffffffffu, s, o);
        warp_c[lane] = iv - v;
        if (lane == 31) s_nc = iv;
        if (lane == 0)  s_G  = s;
    }
    __syncthreads();

    int r = warp_c[wid] + (inc - cnt);
#pragma unroll
    for (int i = 0; i < 4; i++) {
        if (m[i]) { g_bpos[b * SEQ + r] = tid * 4 + i; r++; }
    }
    const int nc = s_nc;
    if (tid == 0) {
        g_nc[b] = nc;
        float G  = s_G / (float)SEQ;
        float Fm = (float)nc / (float)SEQ;
        g_aux[b] = 1.2f * (5.0f * Fm * G + (1.0f - Fm) * (1.0f - G));
    }
    __syncthreads();

#pragma unroll
    for (int i = 0; i < 4; i++) {
        int j = tid * 4 + i;
        float v = 0.f;
        if (j < nc) {
            int pj = g_bpos[b * SEQ + j];
            int pn = (j + 1 < nc) ? g_bpos[b * SEQ + j + 1] : SEQ;
            v = (float)(pn - pj);
        }
        out_cl[b * SEQ + j] = v;
    }
}

// ---------------------------------------------------------------------------
// Kernel 6: downsampled gather + scalar loss
// ---------------------------------------------------------------------------
__global__ void gather_kernel(const float* __restrict__ tokens,
                              float* __restrict__ out_ds,
                              float* __restrict__ out_loss)
{
    const int row = blockIdx.x;
    const int b = row >> 12;
    const int j = row & (SEQ - 1);
    const int tid = threadIdx.x;

    float4* dst = reinterpret_cast<float4*>(out_ds + (size_t)row * DIM);
    if (j < g_nc[b]) {
        int   p = g_bpos[b * SEQ + j];
        float s = g_probs[b * SEQ + p];
        const float4* src = reinterpret_cast<const float4*>(
            tokens + (size_t)(b * SEQ + p) * DIM);
        float4 v0 = src[tid], v1 = src[tid + 128];
        dst[tid]       = make_float4(v0.x * s, v0.y * s, v0.z * s, v0.w * s);
        dst[tid + 128] = make_float4(v1.x * s, v1.y * s, v1.z * s, v1.w * s);
    } else {
        float4 z = make_float4(0.f, 0.f, 0.f, 0.f);
        dst[tid] = z; dst[tid + 128] = z;
    }

    if (row == 0 && tid == 0) {
        float s = 0.f;
#pragma unroll
        for (int i = 0; i < BATCH; i++) s += g_aux[i];
        *out_loss = s * (0.03f / (float)BATCH);
    }
}

// ---------------------------------------------------------------------------
// Launch
// ---------------------------------------------------------------------------
extern "C" void kernel_launch(void* const* d_in, const int* in_sizes, int n_in,
                              void* d_out, int out_size)
{
    const float* tokens    = (const float*)d_in[0];
    const float* W_qk      = (const float*)d_in[1];
    const float* start_key = (const float*)d_in[2];

    float* out      = (float*)d_out;
    float* out_ds   = out;
    float* out_cl   = out + (size_t)NROWS * DIM;
    float* out_loss = out_cl + NROWS;

    dim3 grid(NCOLS / 128, NROWS / 128);   // (16, 256)
    gemm_mma<<<grid, 256>>>(tokens, W_qk);
    cos_kernel<<<NROWS / 8, 256>>>(start_key);
    repair_gemm<<<dim3(32, 16), 256>>>(tokens, W_qk);
    repair_fin<<<128, 256>>>();
    scan_kernel<<<BATCH, 1024>>>(out_cl);
    gather_kernel<<<NROWS, 128>>>(tokens, out_ds, out_loss);

    (void)in_sizes; (void)n_in; (void)out_size;
}

// round 17
// speedup vs baseline: 2.2833x; 1.2094x over previous
#include <cuda_runtime.h>
#include <cuda_fp16.h>
#include <cstdint>
#include <cstddef>

// Problem shape (fixed): B=8, L=4096, D=1024, DK=1024
#define BATCH 8
#define SEQ   4096
#define DIM   1024
#define NCOLS 2048
#define NROWS (BATCH * SEQ)               // 32768
#define K2DIM (DIM / 2)                   // 512

// GEMM: block 128x128, 8 warps (4Mx2N), BK=16, 1-pass fp16, 4-stage cp.async
// Stage (bytes): A[128 rows x 48B (32B data+16 pad)] | B[8 k2-rows x 544B (512+32 pad)]
#define AROW_B   48
#define BROW_B   544
#define OFF_B_B  6144                     // 128*48
#define STAGE_B  10496                    // 6144 + 8*544
#define STAGE_U  (STAGE_B / 4)
#define SMEM_U   (4 * STAGE_U)            // 4 stages, 41984 B total (static)

#define REPCAP 1024
#define WINDOW 2.5e-4f

// ---------------------------------------------------------------------------
// Scratch (no cudaMalloc allowed)
// ---------------------------------------------------------------------------
__device__ float    g_qk[(size_t)NROWS * NCOLS];   // 256 MiB
__device__ uint32_t g_Ah[(size_t)NROWS * K2DIM];   // 64 MiB  [m][k2] half2 (hi)
__device__ uint32_t g_Wh[(size_t)K2DIM * NCOLS];   // 4 MiB   [k2][n] half2 (hi)
__device__ float    g_probs[NROWS];
__device__ int      g_bpos[NROWS];
__device__ int      g_nc[BATCH];
__device__ float    g_aux[BATCH];
__device__ int      g_rep_cnt;
__device__ int      g_rep_rows[REPCAP];
__device__ float    g_rqk[(size_t)REPCAP * 2048];  // 8 MiB exact q|k per repair row

// ---------------------------------------------------------------------------
// Helpers
// ---------------------------------------------------------------------------
__device__ __forceinline__ uint32_t f2h2(float lo, float hi) {
    half2 h = __floats2half2_rn(lo, hi);
    return *reinterpret_cast<uint32_t*>(&h);
}
__device__ __forceinline__ float h1f(float a) {
    return __half2float(__float2half_rn(a));
}
__device__ __forceinline__ void cp16(uint32_t dst, const void* src) {
    asm volatile("cp.async.cg.shared.global [%0], [%1], 16;"
                 :: "r"(dst), "l"(src));
}
__device__ __forceinline__ void ldsm4(uint32_t* r, uint32_t addr) {
    asm volatile("ldmatrix.sync.aligned.m8n8.x4.shared.b16 {%0,%1,%2,%3}, [%4];"
                 : "=r"(r[0]), "=r"(r[1]), "=r"(r[2]), "=r"(r[3]) : "r"(addr));
}
// d += a(16x16 f16) * b(16x8 f16), fp32 accumulate
__device__ __forceinline__ void mma16(float* d, const uint32_t* a, const uint32_t* b) {
    asm volatile(
        "mma.sync.aligned.m16n8k16.row.col.f32.f16.f16.f32 "
        "{%0,%1,%2,%3}, {%4,%5,%6,%7}, {%8,%9}, {%0,%1,%2,%3};"
        : "+f"(d[0]), "+f"(d[1]), "+f"(d[2]), "+f"(d[3])
        : "r"(a[0]), "r"(a[1]), "r"(a[2]), "r"(a[3]), "r"(b[0]), "r"(b[1]));
}

// ---------------------------------------------------------------------------
// Prepass 1: W -> g_Wh packed [k2][n] half2 (low half = even k)
// ---------------------------------------------------------------------------
__global__ void split_w(const float* __restrict__ W)
{
    const int idx = blockIdx.x * blockDim.x + threadIdx.x;   // 0 .. 512*512-1
    const int k2 = idx >> 9;
    const int n4 = (idx & 511) * 4;
    float4 r0 = *reinterpret_cast<const float4*>(W + (size_t)(2 * k2) * NCOLS + n4);
    float4 r1 = *reinterpret_cast<const float4*>(W + (size_t)(2 * k2 + 1) * NCOLS + n4);
    float e0[4] = {r0.x, r0.y, r0.z, r0.w};
    float e1[4] = {r1.x, r1.y, r1.z, r1.w};
    uint32_t hh[4];
#pragma unroll
    for (int j = 0; j < 4; j++) hh[j] = f2h2(h1f(e0[j]), h1f(e1[j]));
    *reinterpret_cast<uint4*>(g_Wh + (size_t)k2 * NCOLS + n4) =
        make_uint4(hh[0], hh[1], hh[2], hh[3]);
}

// ---------------------------------------------------------------------------
// Prepass 2: tokens -> g_Ah packed [m][k2] half2
// ---------------------------------------------------------------------------
__global__ void split_a(const float* __restrict__ A)
{
    const int idx = blockIdx.x * blockDim.x + threadIdx.x;   // 0 .. NROWS*256-1
    const int m  = idx >> 8;
    const int kq = idx & 255;
    float4 v = *reinterpret_cast<const float4*>(A + (size_t)m * DIM + kq * 4);
    *reinterpret_cast<uint2*>(g_Ah + (size_t)m * K2DIM + kq * 2) =
        make_uint2(f2h2(h1f(v.x), h1f(v.y)), f2h2(h1f(v.z), h1f(v.w)));
}

// ---------------------------------------------------------------------------
// Kernel: 1-pass fp16 GEMM, cp.async 4-stage, ldmatrix A frags, 2 CTAs/SM
// grid (NCOLS/128=16, NROWS/128=256), 256 threads
// ---------------------------------------------------------------------------
__global__ void __launch_bounds__(256, 2)
gemm_mma()
{
    __shared__ uint32_t sm[SMEM_U];
    const uint32_t smem_base = (uint32_t)__cvta_generic_to_shared(sm);

    const int tid  = threadIdx.x;
    const int lane = tid & 31;
    const int wid  = tid >> 5;
    const int wm   = wid & 3;
    const int wn   = wid >> 2;
    const int bm   = blockIdx.y * 128;
    const int bn   = blockIdx.x * 128;

    if (blockIdx.x == 0 && blockIdx.y == 0 && tid == 0) g_rep_cnt = 0;

    const int g  = lane >> 2;
    const int tg = lane & 3;

    float acc[2][8][4];
#pragma unroll
    for (int mt = 0; mt < 2; mt++)
#pragma unroll
        for (int nt = 0; nt < 8; nt++)
#pragma unroll
            for (int j = 0; j < 4; j++) acc[mt][nt][j] = 0.f;

    // cp.async decomposition (2 chunks/thread)
    const int a_row  = tid >> 1;          // 0..127
    const int a_part = tid & 1;           // 16B chunk within 32B row
    const int b_row  = tid >> 5;          // 0..7
    const int b_cc   = tid & 31;          // 16B chunk within 512B row

    auto issue = [&](int s) {
        const uint32_t st = smem_base + (uint32_t)((s & 3) * STAGE_B);
        const int k2_0 = s * 8;
        cp16(st + a_row * AROW_B + a_part * 16,
             g_Ah + (size_t)(bm + a_row) * K2DIM + k2_0 + a_part * 4);
        cp16(st + OFF_B_B + b_row * BROW_B + b_cc * 16,
             g_Wh + (size_t)(k2_0 + b_row) * NCOLS + bn + b_cc * 4);
    };

    const int lrow = lane & 15;
    const int lcol = (lane >> 4) * 16;

    // Prologue: fill 3 stages
#pragma unroll
    for (int s = 0; s < 3; s++) {
        issue(s);
        asm volatile("cp.async.commit_group;" ::: "memory");
    }

    const int NST = DIM / 16;   // 64
    for (int s = 0; s < NST; s++) {
        asm volatile("cp.async.wait_group %0;" :: "n"(2) : "memory");
        __syncthreads();
        if (s + 3 < NST) issue(s + 3);
        asm volatile("cp.async.commit_group;" ::: "memory");

        const uint32_t* base  = sm + (s & 3) * STAGE_U;
        const uint32_t  abase = smem_base + (uint32_t)((s & 3) * STAGE_B);

        uint32_t ah[2][4], bh[8][2];
#pragma unroll
        for (int mt = 0; mt < 2; mt++) {
            const uint32_t ad = abase + (wm * 32 + mt * 16 + lrow) * AROW_B + lcol;
            ldsm4(ah[mt], ad);
        }
#pragma unroll
        for (int nt = 0; nt < 8; nt++) {
            const int n = wn * 64 + nt * 8 + g;
            bh[nt][0] = base[OFF_B_B / 4 + tg * (BROW_B / 4) + n];
            bh[nt][1] = base[OFF_B_B / 4 + (tg + 4) * (BROW_B / 4) + n];
        }

#pragma unroll
        for (int nt = 0; nt < 8; nt++)
#pragma unroll
            for (int mt = 0; mt < 2; mt++) mma16(acc[mt][nt], ah[mt], bh[nt]);
    }

    // Epilogue: C fragment -> g_qk
#pragma unroll
    for (int mt = 0; mt < 2; mt++) {
        const int r0 = bm + wm * 32 + mt * 16 + g;
#pragma unroll
        for (int nt = 0; nt < 8; nt++) {
            const int c = bn + wn * 64 + nt * 8 + tg * 2;
            *reinterpret_cast<float2*>(g_qk + (size_t)r0 * NCOLS + c) =
                make_float2(acc[mt][nt][0], acc[mt][nt][1]);
            *reinterpret_cast<float2*>(g_qk + (size_t)(r0 + 8) * NCOLS + c) =
                make_float2(acc[mt][nt][2], acc[mt][nt][3]);
        }
    }
}

// ---------------------------------------------------------------------------
// Kernel: cosine -> probs; flags borderline rows for exact repair
// ---------------------------------------------------------------------------
__global__ void cos_kernel(const float* __restrict__ start_key)
{
    const int gw   = (blockIdx.x * blockDim.x + threadIdx.x) >> 5;
    const int lane = threadIdx.x & 31;
    if (gw >= NROWS) return;
    const int l = gw & (SEQ - 1);

    const float4* q = reinterpret_cast<const float4*>(g_qk + (size_t)gw * NCOLS);
    const float4* kp = (l == 0)
        ? reinterpret_cast<const float4*>(start_key)
        : reinterpret_cast<const float4*>(g_qk + (size_t)(gw - 1) * NCOLS + DIM);

    float dot = 0.f, qq = 0.f, kk = 0.f;
#pragma unroll
    for (int i = 0; i < 8; i++) {
        float4 qv = q[lane + i * 32];
        float4 kv = kp[lane + i * 32];
        dot += qv.x * kv.x + qv.y * kv.y + qv.z * kv.z + qv.w * kv.w;
        qq  += qv.x * qv.x + qv.y * qv.y + qv.z * qv.z + qv.w * qv.w;
        kk  += kv.x * kv.x + kv.y * kv.y + kv.z * kv.z + kv.w * kv.w;
    }
#pragma unroll
    for (int o = 16; o; o >>= 1) {
        dot += __shfl_xor_sync(0xffffffffu, dot, o);
        qq  += __shfl_xor_sync(0xffffffffu, qq,  o);
        kk  += __shfl_xor_sync(0xffffffffu, kk,  o);
    }
    if (lane == 0) {
        float qn = fmaxf(sqrtf(qq), 1e-8f);
        float kn = fmaxf(sqrtf(kk), 1e-8f);
        float p  = (1.0f - dot / (qn * kn)) * 0.5f;
        g_probs[gw] = p;
        if (l != 0 && fabsf(p - 0.5f) < WINDOW) {
            int idx = atomicAdd(&g_rep_cnt, 1);
            if (idx < REPCAP) g_rep_rows[idx] = gw;
        }
    }
}

// ---------------------------------------------------------------------------
// Kernel: gathered exact fp32 GEMM for repair rows
// ---------------------------------------------------------------------------
__global__ void __launch_bounds__(256, 2)
repair_gemm(const float* __restrict__ tokens, const float* __restrict__ W)
{
    const int cnt = min(g_rep_cnt, REPCAP);
    const int i0  = blockIdx.y * 64;
    if (i0 >= cnt) return;

    const int cb      = blockIdx.x;
    const int colbase = cb * 64;
    const bool kside  = cb >= 16;

    __shared__ float As[16][72];
    __shared__ float Bs[16][72];
    __shared__ int   srows[64];

    const int tid = threadIdx.x;
    if (tid < 64) {
        int i = i0 + tid;
        int r = g_rep_rows[(i < cnt) ? i : (cnt - 1)];
        srows[tid] = r - (kside ? 1 : 0);
    }
    __syncthreads();

    const int ty = tid >> 4, tx = tid & 15;
    float acc[4][4];
#pragma unroll
    for (int r = 0; r < 4; r++)
#pragma unroll
        for (int c = 0; c < 4; c++) acc[r][c] = 0.f;

    const int arow = tid >> 2, kq = tid & 3;
    const int bk = tid >> 4, bn4 = (tid & 15) * 4;

    for (int k0 = 0; k0 < DIM; k0 += 16) {
        {
            float4 v = *reinterpret_cast<const float4*>(
                tokens + (size_t)srows[arow] * DIM + k0 + kq * 4);
            As[kq * 4 + 0][arow] = v.x;
            As[kq * 4 + 1][arow] = v.y;
            As[kq * 4 + 2][arow] = v.z;
            As[kq * 4 + 3][arow] = v.w;
        }
        *reinterpret_cast<float4*>(&Bs[bk][bn4]) =
            *reinterpret_cast<const float4*>(
                W + (size_t)(k0 + bk) * NCOLS + colbase + bn4);
        __syncthreads();
#pragma unroll
        for (int k = 0; k < 16; k++) {
            float a[4], b[4];
#pragma unroll
            for (int j = 0; j < 4; j++) { a[j] = As[k][ty * 4 + j]; b[j] = Bs[k][tx * 4 + j]; }
#pragma unroll
            for (int r = 0; r < 4; r++)
#pragma unroll
                for (int c = 0; c < 4; c++) acc[r][c] += a[r] * b[c];
        }
        __syncthreads();
    }

#pragma unroll
    for (int r = 0; r < 4; r++) {
        const int li = i0 + ty * 4 + r;
        if (li < cnt) {
#pragma unroll
            for (int c = 0; c < 4; c++)
                g_rqk[(size_t)li * 2048 + colbase + tx * 4 + c] = acc[r][c];
        }
    }
}

// ---------------------------------------------------------------------------
// Kernel: exact cosine for repair rows -> overwrite probs
// ---------------------------------------------------------------------------
__global__ void repair_fin()
{
    const int cnt  = min(g_rep_cnt, REPCAP);
    const int w    = (blockIdx.x * blockDim.x + threadIdx.x) >> 5;
    const int lane = threadIdx.x & 31;
    if (w >= cnt) return;

    const float4* q = reinterpret_cast<const float4*>(g_rqk + (size_t)w * 2048);
    const float4* k = reinterpret_cast<const float4*>(g_rqk + (size_t)w * 2048 + 1024);

    float dot = 0.f, qq = 0.f, kk = 0.f;
#pragma unroll
    for (int i = 0; i < 8; i++) {
        float4 qv = q[lane + i * 32];
        float4 kv = k[lane + i * 32];
        dot += qv.x * kv.x + qv.y * kv.y + qv.z * kv.z + qv.w * kv.w;
        qq  += qv.x * qv.x + qv.y * qv.y + qv.z * qv.z + qv.w * qv.w;
        kk  += kv.x * kv.x + kv.y * kv.y + kv.z * kv.z + kv.w * kv.w;
    }
#pragma unroll
    for (int o = 16; o; o >>= 1) {
        dot += __shfl_xor_sync(0xffffffffu, dot, o);
        qq  += __shfl_xor_sync(0xffffffffu, qq,  o);
        kk  += __shfl_xor_sync(0xffffffffu, kk,  o);
    }
    if (lane == 0) {
        float qn = fmaxf(sqrtf(qq), 1e-8f);
        float kn = fmaxf(sqrtf(kk), 1e-8f);
        g_probs[g_rep_rows[w]] = (1.0f - dot / (qn * kn)) * 0.5f;
    }
}

// ---------------------------------------------------------------------------
// Kernel: per-batch boundary scan/compaction, chunk_lens, aux partials
// ---------------------------------------------------------------------------
__global__ void __launch_bounds__(1024, 1)
scan_kernel(float* __restrict__ out_cl)
{
    const int b = blockIdx.x;
    const int tid = threadIdx.x;
    const int lane = tid & 31, wid = tid >> 5;

    __shared__ int   warp_c[32];
    __shared__ float warp_s[32];
    __shared__ int   s_nc;
    __shared__ float s_G;

    const float* pr = g_probs + b * SEQ;
    float4 p4 = reinterpret_cast<const float4*>(pr)[tid];
    float p[4] = {p4.x, p4.y, p4.z, p4.w};

    int m[4]; int cnt = 0; float psum = 0.f;
#pragma unroll
    for (int i = 0; i < 4; i++) {
        int l = tid * 4 + i;
        m[i] = (p[i] > 0.5f) || (l == 0);
        cnt += m[i];
        psum += p[i];
    }

    int inc = cnt;
#pragma unroll
    for (int o = 1; o < 32; o <<= 1) {
        int v = __shfl_up_sync(0xffffffffu, inc, o);
        if (lane >= o) inc += v;
    }
    float ws = psum;
#pragma unroll
    for (int o = 16; o; o >>= 1) ws += __shfl_xor_sync(0xffffffffu, ws, o);

    if (lane == 31) warp_c[wid] = inc;
    if (lane == 0)  warp_s[wid] = ws;
    __syncthreads();

    if (wid == 0) {
        int v = warp_c[lane];
        int iv = v;
#pragma unroll
        for (int o = 1; o < 32; o <<= 1) {
            int t = __shfl_up_sync(0xffffffffu, iv, o);
            if (lane >= o) iv += t;
        }
        float s = warp_s[lane];
#pragma unroll
        for (int o = 16; o; o >>= 1) s += __shfl_xor_sync(0xffffffffu, s, o);
        warp_c[lane] = iv - v;
        if (lane == 31) s_nc = iv;
        if (lane == 0)  s_G  = s;
    }
    __syncthreads();

    int r = warp_c[wid] + (inc - cnt);
#pragma unroll
    for (int i = 0; i < 4; i++) {
        if (m[i]) { g_bpos[b * SEQ + r] = tid * 4 + i; r++; }
    }
    const int nc = s_nc;
    if (tid == 0) {
        g_nc[b] = nc;
        float G  = s_G / (float)SEQ;
        float Fm = (float)nc / (float)SEQ;
        g_aux[b] = 1.2f * (5.0f * Fm * G + (1.0f - Fm) * (1.0f - G));
    }
    __syncthreads();

#pragma unroll
    for (int i = 0; i < 4; i++) {
        int j = tid * 4 + i;
        float v = 0.f;
        if (j < nc) {
            int pj = g_bpos[b * SEQ + j];
            int pn = (j + 1 < nc) ? g_bpos[b * SEQ + j + 1] : SEQ;
            v = (float)(pn - pj);
        }
        out_cl[b * SEQ + j] = v;
    }
}

// ---------------------------------------------------------------------------
// Kernel: downsampled gather + scalar loss
// ---------------------------------------------------------------------------
__global__ void gather_kernel(const float* __restrict__ tokens,
                              float* __restrict__ out_ds,
                              float* __restrict__ out_loss)
{
    const int row = blockIdx.x;
    const int b = row >> 12;
    const int j = row & (SEQ - 1);
    const int tid = threadIdx.x;

    float4* dst = reinterpret_cast<float4*>(out_ds + (size_t)row * DIM);
    if (j < g_nc[b]) {
        int   p = g_bpos[b * SEQ + j];
        float s = g_probs[b * SEQ + p];
        const float4* src = reinterpret_cast<const float4*>(
            tokens + (size_t)(b * SEQ + p) * DIM);
        float4 v0 = src[tid], v1 = src[tid + 128];
        dst[tid]       = make_float4(v0.x * s, v0.y * s, v0.z * s, v0.w * s);
        dst[tid + 128] = make_float4(v1.x * s, v1.y * s, v1.z * s, v1.w * s);
    } else {
        float4 z = make_float4(0.f, 0.f, 0.f, 0.f);
        dst[tid] = z; dst[tid + 128] = z;
    }

    if (row == 0 && tid == 0) {
        float s = 0.f;
#pragma unroll
        for (int i = 0; i < BATCH; i++) s += g_aux[i];
        *out_loss = s * (0.03f / (float)BATCH);
    }
}

// ---------------------------------------------------------------------------
// Launch
// ---------------------------------------------------------------------------
extern "C" void kernel_launch(void* const* d_in, const int* in_sizes, int n_in,
                              void* d_out, int out_size)
{
    const float* tokens    = (const float*)d_in[0];
    const float* W_qk      = (const float*)d_in[1];
    const float* start_key = (const float*)d_in[2];

    float* out      = (float*)d_out;
    float* out_ds   = out;
    float* out_cl   = out + (size_t)NROWS * DIM;
    float* out_loss = out_cl + NROWS;

    split_w<<<(K2DIM * 512) / 256, 256>>>(W_qk);        // 1024 blocks
    split_a<<<(NROWS * 256) / 256, 256>>>(tokens);      // 32768 blocks

    dim3 grid(NCOLS / 128, NROWS / 128);   // (16, 256)
    gemm_mma<<<grid, 256>>>();
    cos_kernel<<<NROWS / 8, 256>>>(start_key);
    repair_gemm<<<dim3(32, 16), 256>>>(tokens, W_qk);
    repair_fin<<<128, 256>>>();
    scan_kernel<<<BATCH, 1024>>>(out_cl);
    gather_kernel<<<NROWS, 128>>>(tokens, out_ds, out_loss);

    (void)in_sizes; (void)n_in; (void)out_size;
}